// round 1
// baseline (speedup 1.0000x reference)
#include <cuda_runtime.h>
#include <cuda_bf16.h>
#include <cstdint>

// Problem constants (from reference): N=100000, S=8, B=4, F=128, O=64, E=3.2M
#define MAXN 100000
#define FDIM 128
#define ODIM 64
#define NBAS 4
#define NREL 8

// Scratch (allowed: __device__ globals, no runtime alloc)
__device__ float g_XB[(size_t)NBAS * MAXN * ODIM];   // X @ Bases[b]  : [4, N, 64]  (102.4 MB)
__device__ float g_FW[(size_t)NREL * MAXN * ODIM];   // per-relation  : [8, N, 64]  (204.8 MB)

// ---------------------------------------------------------------------------
// Kernel 1: XB[b] = X @ Bases[b]   (4 GEMMs, fused over b with X tile reuse)
// Block: 128 threads, tile 128 nodes x 64 outs, micro-tile 8x8 (cols split c0, c0+32)
// smem: Xs[128][128] (64KB) + Bs[128][64] (32KB) = 96KB dynamic
// ---------------------------------------------------------------------------
__global__ void __launch_bounds__(128) gemm_xb_kernel(const float* __restrict__ X, 
                                                      const float* __restrict__ bases,
                                                      int nN) {
    extern __shared__ float sm[];
    float* Xs = sm;                  // 128 * 128
    float* Bs = sm + 128 * 128;      // 128 * 64

    const int tid = threadIdx.x;
    const int node0 = blockIdx.x * 128;

    // Load X tile [128 nodes x 128 feats] as float4, zero-fill OOB
    const float4* X4 = (const float4*)X;
    float4* Xs4 = (float4*)Xs;
    #pragma unroll
    for (int i = tid; i < 128 * 32; i += 128) {
        int r = i >> 5, c = i & 31;
        int gn = node0 + r;
        Xs4[i] = (gn < nN) ? X4[(size_t)gn * 32 + c] : make_float4(0.f, 0.f, 0.f, 0.f);
    }

    const int ty = tid >> 3;         // 0..15 -> 8 nodes each
    const int tx = tid & 7;          // 0..7  -> cols {tx*4..+3} and {tx*4+32..+3}
    const int m0 = ty * 8;
    const int c0 = tx * 4;

    for (int b = 0; b < NBAS; b++) {
        __syncthreads();
        // Load basis weights [128 x 64]
        const float4* B4 = (const float4*)(bases + (size_t)b * FDIM * ODIM);
        float4* Bs4 = (float4*)Bs;
        #pragma unroll
        for (int i = tid; i < 2048; i += 128) Bs4[i] = B4[i];
        __syncthreads();

        float acc[8][8];
        #pragma unroll
        for (int i = 0; i < 8; i++)
            #pragma unroll
            for (int j = 0; j < 8; j++) acc[i][j] = 0.f;

        #pragma unroll 1
        for (int kc = 0; kc < 32; kc++) {
            float4 xa[8];
            #pragma unroll
            for (int i = 0; i < 8; i++)
                xa[i] = *(const float4*)(Xs + (m0 + i) * 128 + kc * 4);
            #pragma unroll
            for (int dk = 0; dk < 4; dk++) {
                float4 w0 = *(const float4*)(Bs + (kc * 4 + dk) * 64 + c0);
                float4 w1 = *(const float4*)(Bs + (kc * 4 + dk) * 64 + c0 + 32);
                #pragma unroll
                for (int i = 0; i < 8; i++) {
                    float xk = (dk == 0) ? xa[i].x : (dk == 1) ? xa[i].y
                             : (dk == 2) ? xa[i].z : xa[i].w;
                    acc[i][0] = fmaf(xk, w0.x, acc[i][0]);
                    acc[i][1] = fmaf(xk, w0.y, acc[i][1]);
                    acc[i][2] = fmaf(xk, w0.z, acc[i][2]);
                    acc[i][3] = fmaf(xk, w0.w, acc[i][3]);
                    acc[i][4] = fmaf(xk, w1.x, acc[i][4]);
                    acc[i][5] = fmaf(xk, w1.y, acc[i][5]);
                    acc[i][6] = fmaf(xk, w1.z, acc[i][6]);
                    acc[i][7] = fmaf(xk, w1.w, acc[i][7]);
                }
            }
        }

        // Write XB tile
        #pragma unroll
        for (int i = 0; i < 8; i++) {
            int gn = node0 + m0 + i;
            if (gn < nN) {
                float* dst = g_XB + ((size_t)b * nN + gn) * ODIM;
                *(float4*)(dst + c0)      = make_float4(acc[i][0], acc[i][1], acc[i][2], acc[i][3]);
                *(float4*)(dst + c0 + 32) = make_float4(acc[i][4], acc[i][5], acc[i][6], acc[i][7]);
            }
        }
    }
}

// ---------------------------------------------------------------------------
// Kernel 2: FW[s,n,:] = sum_b comp[s,b] * XB[b,n,:]
// One thread per (node, 4-col group). Each XB element read once, FW written once.
// ---------------------------------------------------------------------------
__global__ void combine_kernel(const float* __restrict__ comp, int nN) {
    int idx = blockIdx.x * blockDim.x + threadIdx.x;
    int total = nN * 16;
    if (idx >= total) return;
    int n = idx >> 4, og = idx & 15;

    float4 xb[NBAS];
    #pragma unroll
    for (int b = 0; b < NBAS; b++)
        xb[b] = *(const float4*)(g_XB + ((size_t)b * nN + n) * ODIM + og * 4);

    float cc[NREL][NBAS];
    #pragma unroll
    for (int s = 0; s < NREL; s++)
        #pragma unroll
        for (int b = 0; b < NBAS; b++) cc[s][b] = __ldg(comp + s * NBAS + b);

    #pragma unroll
    for (int s = 0; s < NREL; s++) {
        float4 r;
        r.x = cc[s][0]*xb[0].x + cc[s][1]*xb[1].x + cc[s][2]*xb[2].x + cc[s][3]*xb[3].x;
        r.y = cc[s][0]*xb[0].y + cc[s][1]*xb[1].y + cc[s][2]*xb[2].y + cc[s][3]*xb[3].y;
        r.z = cc[s][0]*xb[0].z + cc[s][1]*xb[1].z + cc[s][2]*xb[2].z + cc[s][3]*xb[3].z;
        r.w = cc[s][0]*xb[0].w + cc[s][1]*xb[1].w + cc[s][2]*xb[2].w + cc[s][3]*xb[3].w;
        *(float4*)(g_FW + ((size_t)s * nN + n) * ODIM + og * 4) = r;
    }
}

// ---------------------------------------------------------------------------
// Kernel 3: SpMM scatter: out[rows[e]] += vals[e] * FW[cols[e]]
// 16 threads per edge (64 floats = 16 x float4), vectorized red.global.add.v4
// ---------------------------------------------------------------------------
__global__ void spmm_kernel(const int* __restrict__ rows, const int* __restrict__ cols,
                            const float* __restrict__ vals, float* __restrict__ out, int E) {
    int t = blockIdx.x * blockDim.x + threadIdx.x;
    int e = t >> 4;
    if (e >= E) return;
    int l = t & 15;
    int c = __ldg(cols + e);
    int r = __ldg(rows + e);
    float v = __ldg(vals + e);
    float4 m = *(const float4*)(g_FW + (size_t)c * ODIM + l * 4);
    m.x *= v; m.y *= v; m.z *= v; m.w *= v;
    float* dst = out + (size_t)r * ODIM + l * 4;
    asm volatile("red.global.add.v4.f32 [%0], {%1,%2,%3,%4};"
                 :: "l"(dst), "f"(m.x), "f"(m.y), "f"(m.z), "f"(m.w) : "memory");
}

// ---------------------------------------------------------------------------
// Kernel 4: out = relu(out + b)
// ---------------------------------------------------------------------------
__global__ void bias_relu_kernel(float* __restrict__ out, const float* __restrict__ bias, int nN) {
    int idx = blockIdx.x * blockDim.x + threadIdx.x;
    int total = nN * 16;
    if (idx >= total) return;
    float4 v = ((float4*)out)[idx];
    int og = idx & 15;
    float4 bb = __ldg((const float4*)bias + og);
    v.x = fmaxf(v.x + bb.x, 0.f);
    v.y = fmaxf(v.y + bb.y, 0.f);
    v.z = fmaxf(v.z + bb.z, 0.f);
    v.w = fmaxf(v.w + bb.w, 0.f);
    ((float4*)out)[idx] = v;
}

// ---------------------------------------------------------------------------
extern "C" void kernel_launch(void* const* d_in, const int* in_sizes, int n_in,
                              void* d_out, int out_size) {
    const float* X     = (const float*)d_in[0];   // [N, 128]
    const int*   rows  = (const int*)  d_in[1];   // [E]
    const int*   cols  = (const int*)  d_in[2];   // [E]
    const float* vals  = (const float*)d_in[3];   // [E]
    const float* bases = (const float*)d_in[4];   // [4, 128, 64]
    const float* comp  = (const float*)d_in[5];   // [8, 4]
    const float* bias  = (const float*)d_in[6];   // [64]
    float* out = (float*)d_out;                   // [N, 64]

    int nN = in_sizes[0] / FDIM;
    int E  = in_sizes[1];

    cudaFuncSetAttribute(gemm_xb_kernel, cudaFuncAttributeMaxDynamicSharedMemorySize, 96 * 1024);

    // out accumulates atomically -> zero it first (memset node is capturable)
    cudaMemsetAsync(out, 0, (size_t)nN * ODIM * sizeof(float));

    int gblocks = (nN + 127) / 128;
    gemm_xb_kernel<<<gblocks, 128, 96 * 1024>>>(X, bases, nN);

    combine_kernel<<<(nN * 16 + 255) / 256, 256>>>(comp, nN);

    long long spthreads = (long long)E * 16;
    spmm_kernel<<<(int)((spthreads + 255) / 256), 256>>>(rows, cols, vals, out, E);

    bias_relu_kernel<<<(nN * 16 + 255) / 256, 256>>>(out, bias, nN);
}

// round 3
// speedup vs baseline: 1.0862x; 1.0862x over previous
#include <cuda_runtime.h>
#include <cuda_bf16.h>
#include <cstdint>

// Problem constants: N=100000, S=8, B=4, F=128, O=64, E=3.2M
#define MAXN 100000
#define FDIM 128
#define ODIM 64
#define NBAS 4
#define NREL 8

// Scratch (__device__ globals; no runtime alloc allowed)
__device__ float g_FW[(size_t)NREL * MAXN * ODIM];  // [8, N, 64] per-relation feats
__device__ float g_W[NREL * ODIM * FDIM];           // [8][n=64][k=128] tf32-rounded bits

// ---------------------------------------------------------------------------
__device__ __forceinline__ uint32_t f2tf32(float v) {
    uint32_t t;
    asm("cvt.rna.tf32.f32 %0, %1;" : "=r"(t) : "f"(v));
    return t;
}

__device__ __forceinline__ void mma_tf32(float* d, uint32_t a0, uint32_t a1, uint32_t a2,
                                         uint32_t a3, uint32_t b0, uint32_t b1) {
    asm volatile(
        "mma.sync.aligned.m16n8k8.row.col.f32.tf32.tf32.f32 "
        "{%0,%1,%2,%3}, {%4,%5,%6,%7}, {%8,%9}, {%0,%1,%2,%3};"
        : "+f"(d[0]), "+f"(d[1]), "+f"(d[2]), "+f"(d[3])
        : "r"(a0), "r"(a1), "r"(a2), "r"(a3), "r"(b0), "r"(b1));
}

// ---------------------------------------------------------------------------
// Kernel 0: W[s][n][k] = tf32( sum_b comp[s,b] * Bases[b][k][n] )
// ---------------------------------------------------------------------------
__global__ void wcomb_kernel(const float* __restrict__ bases, const float* __restrict__ comp) {
    int idx = blockIdx.x * blockDim.x + threadIdx.x;
    if (idx >= NREL * FDIM * ODIM) return;
    int s = idx >> 13;
    int r = idx & 8191;
    int n = r >> 7;            // 0..63  (output col)
    int k = r & 127;           // 0..127 (input feat)
    float acc = 0.f;
    #pragma unroll
    for (int b = 0; b < NBAS; b++)
        acc += __ldg(comp + s * NBAS + b) * __ldg(bases + b * FDIM * ODIM + k * ODIM + n);
    g_W[idx] = __uint_as_float(f2tf32(acc));
}

// ---------------------------------------------------------------------------
// Kernel 1: FW[s] = X @ W[s]^T via mma.sync tf32 (X split hi/lo for accuracy)
// Block: 128 threads (4 warps), tile 128 rows x 64 cols, K=128.
// smem: Xs fp32 [128][132] (67.6KB) + Ws tf32 [64][132] (33.8KB) = 101376 B
// ---------------------------------------------------------------------------
#define XS_STRIDE 132
#define WS_STRIDE 132
#define SMEM_GEMM (128 * XS_STRIDE * 4 + 64 * WS_STRIDE * 4)

__global__ void __launch_bounds__(128) gemm_fw_kernel(const float* __restrict__ X, int nN) {
    extern __shared__ float sm[];
    float* Xs = sm;                         // [128][132] full fp32
    float* Ws = sm + 128 * XS_STRIDE;       // [64][132]  tf32 bits

    const int tid = threadIdx.x;
    const int wid = tid >> 5;
    const int lane = tid & 31;
    const int g = lane >> 2;                // group id 0..7
    const int tg = lane & 3;                // thread-in-group 0..3
    const int node0 = blockIdx.x * 128;
    const int wrow = wid * 32;              // warp's local row base

    // Load X tile [128 x 128] fp32 (coalesced float4), pad-strided
    {
        const float4* X4 = (const float4*)X;
        #pragma unroll 4
        for (int i = tid; i < 4096; i += 128) {
            int row = i >> 5, q = i & 31;
            int gn = node0 + row;
            float4 v = (gn < nN) ? X4[(size_t)gn * 32 + q] : make_float4(0.f, 0.f, 0.f, 0.f);
            *(float4*)(Xs + row * XS_STRIDE + q * 4) = v;
        }
    }

    for (int s = 0; s < NREL; s++) {
        __syncthreads();   // previous iter's smem reads done before overwrite
        // Load W_s [64 n][128 k] -> padded smem (2048 float4)
        {
            const float4* src = (const float4*)(g_W + s * ODIM * FDIM);
            #pragma unroll 4
            for (int i = tid; i < 2048; i += 128) {
                int n = i >> 5, q = i & 31;
                *(float4*)(Ws + n * WS_STRIDE + q * 4) = src[i];
            }
        }
        __syncthreads();

        float d[2][8][4];
        #pragma unroll
        for (int mi = 0; mi < 2; mi++)
            #pragma unroll
            for (int ni = 0; ni < 8; ni++)
                #pragma unroll
                for (int j = 0; j < 4; j++) d[mi][ni][j] = 0.f;

        #pragma unroll 2
        for (int ks = 0; ks < 16; ks++) {
            // A fragments (hi/lo split). a0:(g,tg) a1:(g+8,tg) a2:(g,tg+4) a3:(g+8,tg+4)
            uint32_t ah[2][4], al[2][4];
            #pragma unroll
            for (int mi = 0; mi < 2; mi++) {
                const float* ar = Xs + (wrow + mi * 16 + g) * XS_STRIDE + ks * 8 + tg;
                float x0 = ar[0];
                float x1 = ar[8 * XS_STRIDE];
                float x2 = ar[4];
                float x3 = ar[8 * XS_STRIDE + 4];
                ah[mi][0] = f2tf32(x0); al[mi][0] = f2tf32(x0 - __uint_as_float(ah[mi][0]));
                ah[mi][1] = f2tf32(x1); al[mi][1] = f2tf32(x1 - __uint_as_float(ah[mi][1]));
                ah[mi][2] = f2tf32(x2); al[mi][2] = f2tf32(x2 - __uint_as_float(ah[mi][2]));
                ah[mi][3] = f2tf32(x3); al[mi][3] = f2tf32(x3 - __uint_as_float(ah[mi][3]));
            }
            #pragma unroll
            for (int ni = 0; ni < 8; ni++) {
                // B fragments: b0:(k=ks*8+tg, n=ni*8+g), b1:(k+4)
                const float* br = Ws + (ni * 8 + g) * WS_STRIDE + ks * 8 + tg;
                uint32_t b0 = __float_as_uint(br[0]);
                uint32_t b1 = __float_as_uint(br[4]);
                #pragma unroll
                for (int mi = 0; mi < 2; mi++) {
                    mma_tf32(d[mi][ni], ah[mi][0], ah[mi][1], ah[mi][2], ah[mi][3], b0, b1);
                    mma_tf32(d[mi][ni], al[mi][0], al[mi][1], al[mi][2], al[mi][3], b0, b1);
                }
            }
        }

        // Direct stores: c0,c1 at (row=base+g, col=ni*8+tg*2); c2,c3 at row+8
        {
            float* fwbase = g_FW + (size_t)s * nN * ODIM;
            #pragma unroll
            for (int mi = 0; mi < 2; mi++) {
                int r0 = node0 + wrow + mi * 16 + g;
                int r1 = r0 + 8;
                #pragma unroll
                for (int ni = 0; ni < 8; ni++) {
                    int c = ni * 8 + tg * 2;
                    if (r0 < nN)
                        *(float2*)(fwbase + (size_t)r0 * ODIM + c) = make_float2(d[mi][ni][0], d[mi][ni][1]);
                    if (r1 < nN)
                        *(float2*)(fwbase + (size_t)r1 * ODIM + c) = make_float2(d[mi][ni][2], d[mi][ni][3]);
                }
            }
        }
    }
}

// ---------------------------------------------------------------------------
// Kernel 2: SpMM scatter: out[rows[e]] += vals[e] * FW[cols[e]]  (vector REDG)
// ---------------------------------------------------------------------------
__global__ void spmm_kernel(const int* __restrict__ rows, const int* __restrict__ cols,
                            const float* __restrict__ vals, float* __restrict__ out, int E) {
    int t = blockIdx.x * blockDim.x + threadIdx.x;
    int e = t >> 4;
    if (e >= E) return;
    int l = t & 15;
    int c = __ldg(cols + e);
    int r = __ldg(rows + e);
    float v = __ldg(vals + e);
    float4 m = *(const float4*)(g_FW + (size_t)c * ODIM + l * 4);
    m.x *= v; m.y *= v; m.z *= v; m.w *= v;
    float* dst = out + (size_t)r * ODIM + l * 4;
    asm volatile("red.global.add.v4.f32 [%0], {%1,%2,%3,%4};"
                 :: "l"(dst), "f"(m.x), "f"(m.y), "f"(m.z), "f"(m.w) : "memory");
}

// ---------------------------------------------------------------------------
// Kernel 3: out = relu(out + bias)
// ---------------------------------------------------------------------------
__global__ void bias_relu_kernel(float* __restrict__ out, const float* __restrict__ bias, int nN) {
    int idx = blockIdx.x * blockDim.x + threadIdx.x;
    int total = nN * 16;
    if (idx >= total) return;
    float4 v = ((float4*)out)[idx];
    int og = idx & 15;
    float4 bb = __ldg((const float4*)bias + og);
    v.x = fmaxf(v.x + bb.x, 0.f);
    v.y = fmaxf(v.y + bb.y, 0.f);
    v.z = fmaxf(v.z + bb.z, 0.f);
    v.w = fmaxf(v.w + bb.w, 0.f);
    ((float4*)out)[idx] = v;
}

// ---------------------------------------------------------------------------
extern "C" void kernel_launch(void* const* d_in, const int* in_sizes, int n_in,
                              void* d_out, int out_size) {
    const float* X     = (const float*)d_in[0];   // [N, 128]
    const int*   rows  = (const int*)  d_in[1];   // [E]
    const int*   cols  = (const int*)  d_in[2];   // [E]
    const float* vals  = (const float*)d_in[3];   // [E]
    const float* bases = (const float*)d_in[4];   // [4, 128, 64]
    const float* comp  = (const float*)d_in[5];   // [8, 4]
    const float* bias  = (const float*)d_in[6];   // [64]
    float* out = (float*)d_out;                   // [N, 64]

    int nN = in_sizes[0] / FDIM;
    int E  = in_sizes[1];

    cudaFuncSetAttribute(gemm_fw_kernel, cudaFuncAttributeMaxDynamicSharedMemorySize, SMEM_GEMM);

    cudaMemsetAsync(out, 0, (size_t)nN * ODIM * sizeof(float));

    wcomb_kernel<<<(NREL * FDIM * ODIM + 255) / 256, 256>>>(bases, comp);

    int gblocks = (nN + 127) / 128;
    gemm_fw_kernel<<<gblocks, 128, SMEM_GEMM>>>(X, nN);

    long long spthreads = (long long)E * 16;
    spmm_kernel<<<(int)((spthreads + 255) / 256), 256>>>(rows, cols, vals, out, E);

    bias_relu_kernel<<<(nN * 16 + 255) / 256, 256>>>(out, bias, nN);
}